// round 4
// baseline (speedup 1.0000x reference)
#include <cuda_runtime.h>

// LTC MemoryCell: B=32, T=128, d=128, units=256, ODE_UNFOLDS=6.
// Each (v[b,j], v[b,j+d]) pair is an independent 2-dim recurrence; one thread
// per (b,j), all params in registers.
//
// R4: tanh.approx is quarter-rate MUFU (rt~16) => 4-tanh/unfold floor ~84 cyc.
// Switch to ex2 (rt 8) sigmoids with a shared-denominator rewrite: multiply
// num & den by Pf=(1+e_self)(1+e_cross) so ONE rcp per target serves both
// synapse sigmoids AND the unfold division:
//   v' = [(nb + cmt*v)*Pf + Tn] / [db*Pf + Sn]
//   Sn = wsum + w_self*e_cross + w_cross*e_self   (and Tn with w*erev)
// Per unfold: 4 ex2 + 2 rcp (all rt 8) = 48 port cyc, chain ~68.

#define Dn      128
#define UNITS   256
#define Tn      128
#define UNFOLDS 6
#define EPSc    1e-8f
#define L2E     1.4426950408889634f

__device__ __forceinline__ float ex2f(float x) {
    float y; asm("ex2.approx.ftz.f32 %0, %1;" : "=f"(y) : "f"(x)); return y;
}
__device__ __forceinline__ float rcpf(float x) {
    float y; asm("rcp.approx.ftz.f32 %0, %1;" : "=f"(y) : "f"(x)); return y;
}

__global__ void __launch_bounds__(Dn, 1) ltc_kernel(
    const float* __restrict__ X,       // (B,T,d)
    const float* __restrict__ in_w,    // (d)
    const float* __restrict__ in_b,    // (d)
    const float* __restrict__ out_w,   // (d)
    const float* __restrict__ out_b,   // (d)
    const float* __restrict__ gleak,   // (units)
    const float* __restrict__ vleak,   // (units)
    const float* __restrict__ cm,      // (units)
    const float* __restrict__ w,       // (units,units)
    const float* __restrict__ mu,      // (units,units)
    const float* __restrict__ sigma,   // (units,units)
    const float* __restrict__ erev,    // (units,units)
    const float* __restrict__ sw,      // (d,units)
    const float* __restrict__ smu,     // (d,units)
    const float* __restrict__ ssig,    // (d,units)
    const float* __restrict__ serev,   // (d,units)
    float* __restrict__ out)           // (B,d)
{
    const int j  = threadIdx.x;        // pair index, 0..d-1
    const int b  = blockIdx.x;         // batch index
    const int jc = j + Dn;             // partner unit

    // synapse flat indices (row-major (src, tgt))
    const int i_aa = j  * UNITS + j;   // j   -> j
    const int i_ca = jc * UNITS + j;   // j+d -> j
    const int i_cc = jc * UNITS + jc;  // j+d -> j+d
    const int i_ac = j  * UNITS + jc;  // j   -> j+d

    // sigmoid((v-mu)*sig) = 1/(1+e), e = 2^q, q = -sig*L2E*v + mu*sig*L2E
    float sg, m;
    sg = __ldg(sigma + i_aa); m = __ldg(mu + i_aa);
    const float cq1_aa = -sg * L2E, cq0_aa = m * sg * L2E;
    sg = __ldg(sigma + i_ca); m = __ldg(mu + i_ca);
    const float cq1_ca = -sg * L2E, cq0_ca = m * sg * L2E;
    sg = __ldg(sigma + i_cc); m = __ldg(mu + i_cc);
    const float cq1_cc = -sg * L2E, cq0_cc = m * sg * L2E;
    sg = __ldg(sigma + i_ac); m = __ldg(mu + i_ac);
    const float cq1_ac = -sg * L2E, cq0_ac = m * sg * L2E;

    const float w_aa = __ldg(w + i_aa), we_aa = w_aa * __ldg(erev + i_aa);
    const float w_ca = __ldg(w + i_ca), we_ca = w_ca * __ldg(erev + i_ca);
    const float w_cc = __ldg(w + i_cc), we_cc = w_cc * __ldg(erev + i_cc);
    const float w_ac = __ldg(w + i_ac), we_ac = w_ac * __ldg(erev + i_ac);

    const float wsumA  = w_aa + w_ca,  wesumA = we_aa + we_ca;
    const float wsumC  = w_cc + w_ac,  wesumC = we_cc + we_ac;

    // sensory synapses: src j -> tgt j (A) and src j -> tgt j+d (C)
    const int is_a = j * UNITS + j;
    const int is_c = j * UNITS + jc;
    sg = __ldg(ssig + is_a); m = __ldg(smu + is_a);
    const float sc1A = -sg * L2E, sc0A = m * sg * L2E;
    sg = __ldg(ssig + is_c); m = __ldg(smu + is_c);
    const float sc1C = -sg * L2E, sc0C = m * sg * L2E;
    const float swA = __ldg(sw + is_a), serA = __ldg(serev + is_a);
    const float swC = __ldg(sw + is_c), serC = __ldg(serev + is_c);

    // per-unit params
    const float glA = __ldg(gleak + j),  glC = __ldg(gleak + jc);
    const float vlA = __ldg(vleak + j),  vlC = __ldg(vleak + jc);
    const float cmtA = __ldg(cm + j)  * (float)UNFOLDS;
    const float cmtC = __ldg(cm + jc) * (float)UNFOLDS;

    const float numBaseA = glA * vlA;                 // gleak*vleak
    const float numBaseC = glC * vlC;
    const float denBaseA = cmtA + glA + EPSc;         // cm_t + gleak (+eps)
    const float denBaseC = cmtC + glC + EPSc;

    const float inw = __ldg(in_w + j), inb = __ldg(in_b + j);
    const float ow  = __ldg(out_w + j), ob = __ldg(out_b + j);

    const float* xp = X + ((size_t)b * Tn) * Dn + j;

    float vA = 0.0f, vC = 0.0f;

    // ---- software-pipelined sensory state (computed one timestep ahead) ----
    // sa = sw / (1 + es); nb = numBase + sa*serev; db = denBase + sa
    float xt0 = fmaf(__ldg(xp), inw, inb);
    float es, sa;
    es = ex2f(fmaf(sc1A, xt0, sc0A));
    sa = swA * rcpf(1.0f + es);
    float nbA = fmaf(sa, serA, numBaseA);
    float dbA = denBaseA + sa;
    es = ex2f(fmaf(sc1C, xt0, sc0C));
    sa = swC * rcpf(1.0f + es);
    float nbC = fmaf(sa, serC, numBaseC);
    float dbC = denBaseC + sa;

    float xnext = __ldg(xp + Dn);        // raw x for t=1

    #pragma unroll 2
    for (int t = 0; t < Tn; ++t) {
        // ---- NEXT timestep's sensory bases (independent of v; sinks into
        //      the unfold-chain stalls) ----
        const float xtn = fmaf(xnext, inw, inb);
        const float esA_n = ex2f(fmaf(sc1A, xtn, sc0A));
        const float esC_n = ex2f(fmaf(sc1C, xtn, sc0C));
        const float saA_n = swA * rcpf(1.0f + esA_n);
        const float saC_n = swC * rcpf(1.0f + esC_n);
        const float nbA_n = fmaf(saA_n, serA, numBaseA);
        const float dbA_n = denBaseA + saA_n;
        const float nbC_n = fmaf(saC_n, serC, numBaseC);
        const float dbC_n = denBaseC + saC_n;
        {   // branchless prefetch of x for t+2
            const int tnn = (t + 2 < Tn) ? (t + 2) : (Tn - 1);
            xnext = __ldg(xp + tnn * Dn);
        }

        #pragma unroll
        for (int u = 0; u < UNFOLDS; ++u) {
            // sigmoid args (2 per source v)
            const float qAA = fmaf(cq1_aa, vA, cq0_aa);
            const float qCA = fmaf(cq1_ca, vC, cq0_ca);
            const float qAC = fmaf(cq1_ac, vA, cq0_ac);
            const float qCC = fmaf(cq1_cc, vC, cq0_cc);
            const float eAA = ex2f(qAA);
            const float eCA = ex2f(qCA);
            const float eAC = ex2f(qAC);
            const float eCC = ex2f(qCC);

            // off-chain partials in the ex2 shadow
            const float uA = fmaf(cmtA, vA, nbA);
            const float uC = fmaf(cmtC, vC, nbC);

            // target A: self term eAA, cross term eCA
            const float aA  = 1.0f + eAA;
            const float PfA = fmaf(aA, eCA, aA);            // (1+eAA)(1+eCA)
            const float SnA = fmaf(w_aa, eCA, fmaf(w_ca, eAA, wsumA));
            const float TnA = fmaf(we_aa, eCA, fmaf(we_ca, eAA, wesumA));
            const float NA  = fmaf(uA, PfA, TnA);
            const float BA  = fmaf(dbA, PfA, SnA);

            // target C: self term eCC, cross term eAC
            const float aC  = 1.0f + eCC;
            const float PfC = fmaf(aC, eAC, aC);            // (1+eCC)(1+eAC)
            const float SnC = fmaf(w_cc, eAC, fmaf(w_ac, eCC, wsumC));
            const float TnC = fmaf(we_cc, eAC, fmaf(we_ac, eCC, wesumC));
            const float NC  = fmaf(uC, PfC, TnC);
            const float BC  = fmaf(dbC, PfC, SnC);

            vA = NA * rcpf(BA);
            vC = NC * rcpf(BC);
        }

        // rotate pipelined sensory state
        nbA = nbA_n; dbA = dbA_n;
        nbC = nbC_n; dbC = dbC_n;
    }

    out[b * Dn + j] = fmaf(vA, ow, ob);
}

extern "C" void kernel_launch(void* const* d_in, const int* in_sizes, int n_in,
                              void* d_out, int out_size) {
    const float* X     = (const float*)d_in[0];
    const float* in_w  = (const float*)d_in[1];
    const float* in_b  = (const float*)d_in[2];
    const float* out_w = (const float*)d_in[3];
    const float* out_b = (const float*)d_in[4];
    const float* gleak = (const float*)d_in[5];
    const float* vleak = (const float*)d_in[6];
    const float* cmp   = (const float*)d_in[7];
    const float* w     = (const float*)d_in[8];
    const float* mu    = (const float*)d_in[9];
    const float* sigma = (const float*)d_in[10];
    const float* erev  = (const float*)d_in[11];
    const float* sw    = (const float*)d_in[12];
    const float* smu   = (const float*)d_in[13];
    const float* ssig  = (const float*)d_in[14];
    const float* serev = (const float*)d_in[15];
    float* out = (float*)d_out;

    const int B = in_sizes[0] / (Tn * Dn);   // 32
    ltc_kernel<<<B, Dn>>>(X, in_w, in_b, out_w, out_b,
                          gleak, vleak, cmp, w, mu, sigma, erev,
                          sw, smu, ssig, serev, out);
}